// round 10
// baseline (speedup 1.0000x reference)
#include <cuda_runtime.h>
#include <cuda_bf16.h>
#include <math.h>

// Problem constants
#define BS      4
#define SEQ     1024
#define DIM     1024
#define N_HEADS 16
#define D_HEAD  64
#define MROWS   (BS * SEQ)      // 4096

// ---------------------------------------------------------------------------
// Scratch (static device globals; no runtime allocation allowed)
// ---------------------------------------------------------------------------
__device__ float g_q  [MROWS * DIM];
__device__ float g_k  [MROWS * DIM];
__device__ float g_v  [MROWS * DIM];
__device__ float g_ctx[MROWS * DIM];

// ---------------------------------------------------------------------------
// Common tf32 helpers
// ---------------------------------------------------------------------------
__device__ __forceinline__ unsigned f2tf32(float f) {
    unsigned u;
    asm("cvt.rna.tf32.f32 %0, %1;" : "=r"(u) : "f"(f));
    return u;
}

__device__ __forceinline__ void mma_tf32(float c[4],
    unsigned a0, unsigned a1, unsigned a2, unsigned a3,
    unsigned b0, unsigned b1)
{
    asm volatile(
        "mma.sync.aligned.m16n8k8.row.col.f32.tf32.tf32.f32 "
        "{%0,%1,%2,%3}, {%4,%5,%6,%7}, {%8,%9}, {%0,%1,%2,%3};"
        : "+f"(c[0]), "+f"(c[1]), "+f"(c[2]), "+f"(c[3])
        : "r"(a0), "r"(a1), "r"(a2), "r"(a3), "r"(b0), "r"(b1));
}

// Fast 2^x on the FMA/ALU pipes (no MUFU). Valid for x in [-100, 100];
// clamps outside. Rel err ~3e-6 (degree-5 Taylor on f in [-0.5, 0.5]).
#define LOG2E 1.4426950408889634f
__device__ __forceinline__ float fast_exp2(float x) {
    x = fminf(fmaxf(x, -100.0f), 100.0f);
    float z = x + 12582912.0f;                 // 1.5*2^23: round-to-nearest int
    int   n = __float_as_int(z) - 0x4B400000;  // n = round(x)
    float f = x - (z - 12582912.0f);           // f in [-0.5, 0.5]
    float p =            1.3333558e-3f;
    p = fmaf(p, f, 9.6181291e-3f);
    p = fmaf(p, f, 5.5504109e-2f);
    p = fmaf(p, f, 2.4022650e-1f);
    p = fmaf(p, f, 6.9314718e-1f);
    p = fmaf(p, f, 1.0f);                      // p in [0.707, 1.415)
    return __int_as_float(__float_as_int(p) + (n << 23));
}

// ---------------------------------------------------------------------------
// TF32 tensor-core GEMM: C = alpha * (A @ B + bias)
// A: MxK row-major, B: KxN row-major (N = DIM), bias: N
// Block tile 128x128, BK=16, 256 threads = 8 warps (2x4), warp tile 64x32.
// 2 blocks/SM (34.8KB smem, <=128 regs): cross-block overlap hides the
// per-BK-tile __syncthreads and LDS->MMA latency (R9 GEMM was 1 block of
// 512 thr -> all warps stalled together at every barrier; issue-bound).
// Grid (8, 32) = 256 blocks = one wave at 2/SM on 148 SMs.
// Smem: As[2][16][136], Bs[2][16][136]  (136 % 32 == 8 -> conflict-free).
// ---------------------------------------------------------------------------
#define GBM 128
#define GBN 128
#define GBK 16
#define GSTR 136
#define GEMM_BUF (GBK * GSTR)                       // 2176 words / buffer
#define GEMM_SMEM_WORDS (4 * GEMM_BUF)              // 8704
#define GEMM_SMEM_BYTES (GEMM_SMEM_WORDS * 4)       // 34816

__global__ __launch_bounds__(256, 2) void tf32_gemm_kernel(
    const float* __restrict__ A, const float* __restrict__ B,
    const float* __restrict__ bias, float* __restrict__ C,
    float alpha)
{
    extern __shared__ unsigned gsm[];
    unsigned* const AsBase = gsm;                    // 2 x GEMM_BUF
    unsigned* const BsBase = gsm + 2 * GEMM_BUF;     // 2 x GEMM_BUF

    const int tid  = threadIdx.x;
    const int lane = tid & 31;
    const int wid  = tid >> 5;        // 0..7
    const int gid  = lane >> 2;       // 0..7
    const int tg   = lane & 3;        // 0..3

    const int warp_m = wid & 1;       // 0..1
    const int warp_n = wid >> 1;      // 0..3
    const int mb = warp_m * 64;
    const int nb = warp_n * 32;

    const int bx = blockIdx.x;        // N tile
    const int by = blockIdx.y;        // M tile

    const float* Ab = A + (size_t)by * GBM * DIM;    // K == DIM == 1024
    const float* Bb = B + (size_t)bx * GBN;

    // global-load mapping
    // A tile: 128 rows x 16 cols = 2048 words -> 2 float4 / thread
    const int a_row = tid & 127;              // 0..127
    const int a_cb  = (tid >> 7) * 8;         // 0 or 8 (float4 at +0, +4)
    // B tile: 16 rows x 128 cols = 2048 words -> 2 float4 / thread
    const int b_row = tid >> 5;               // 0..7 (second row = +8)
    const int b_col = (tid & 31) * 4;         // 0..124

    float acc[4][4][4];
    #pragma unroll
    for (int t = 0; t < 4; t++)
        #pragma unroll
        for (int u = 0; u < 4; u++)
            #pragma unroll
            for (int r = 0; r < 4; r++)
                acc[t][u][r] = 0.f;

    float4 pa0, pa1, pb0, pb1;

    // ---- preload tile 0 ----
    pa0 = *(const float4*)(Ab + (size_t)a_row * DIM + a_cb);
    pa1 = *(const float4*)(Ab + (size_t)a_row * DIM + a_cb + 4);
    pb0 = *(const float4*)(Bb + (size_t)b_row * DIM + b_col);
    pb1 = *(const float4*)(Bb + (size_t)(b_row + 8) * DIM + b_col);
    {
        unsigned* As0 = AsBase;
        unsigned* Bs0 = BsBase;
        As0[(a_cb + 0) * GSTR + a_row] = f2tf32(pa0.x);
        As0[(a_cb + 1) * GSTR + a_row] = f2tf32(pa0.y);
        As0[(a_cb + 2) * GSTR + a_row] = f2tf32(pa0.z);
        As0[(a_cb + 3) * GSTR + a_row] = f2tf32(pa0.w);
        As0[(a_cb + 4) * GSTR + a_row] = f2tf32(pa1.x);
        As0[(a_cb + 5) * GSTR + a_row] = f2tf32(pa1.y);
        As0[(a_cb + 6) * GSTR + a_row] = f2tf32(pa1.z);
        As0[(a_cb + 7) * GSTR + a_row] = f2tf32(pa1.w);
        uint4 bv;
        bv.x = f2tf32(pb0.x); bv.y = f2tf32(pb0.y);
        bv.z = f2tf32(pb0.z); bv.w = f2tf32(pb0.w);
        *(uint4*)(&Bs0[b_row * GSTR + b_col]) = bv;
        bv.x = f2tf32(pb1.x); bv.y = f2tf32(pb1.y);
        bv.z = f2tf32(pb1.z); bv.w = f2tf32(pb1.w);
        *(uint4*)(&Bs0[(b_row + 8) * GSTR + b_col]) = bv;
    }
    __syncthreads();

    const int NT = DIM / GBK;     // 64 tiles
    int cur = 0;
    for (int t0 = 0; t0 < NT; t0++) {
        const bool has_next = (t0 + 1) < NT;
        if (has_next) {
            const int kn = (t0 + 1) * GBK;
            pa0 = *(const float4*)(Ab + (size_t)a_row * DIM + kn + a_cb);
            pa1 = *(const float4*)(Ab + (size_t)a_row * DIM + kn + a_cb + 4);
            pb0 = *(const float4*)(Bb + (size_t)(kn + b_row) * DIM + b_col);
            pb1 = *(const float4*)(Bb + (size_t)(kn + b_row + 8) * DIM + b_col);
        }

        // ---- compute: 2 k8-steps over this tile ----
        const unsigned* Asc = AsBase + cur * GEMM_BUF;
        const unsigned* Bsc = BsBase + cur * GEMM_BUF;
        #pragma unroll
        for (int kb = 0; kb < GBK; kb += 8) {
            unsigned af0[4], af1[4], af2[4], af3[4], bf0[4], bf1[4];
            #pragma unroll
            for (int t = 0; t < 4; t++) {
                const int m0 = mb + t * 16 + gid;
                af0[t] = Asc[(kb + tg    ) * GSTR + m0];
                af1[t] = Asc[(kb + tg    ) * GSTR + m0 + 8];
                af2[t] = Asc[(kb + tg + 4) * GSTR + m0];
                af3[t] = Asc[(kb + tg + 4) * GSTR + m0 + 8];
            }
            #pragma unroll
            for (int u = 0; u < 4; u++) {
                const int n0 = nb + u * 8 + gid;
                bf0[u] = Bsc[(kb + tg    ) * GSTR + n0];
                bf1[u] = Bsc[(kb + tg + 4) * GSTR + n0];
            }
            #pragma unroll
            for (int t = 0; t < 4; t++)
                #pragma unroll
                for (int u = 0; u < 4; u++)
                    mma_tf32(acc[t][u], af0[t], af1[t], af2[t], af3[t],
                             bf0[u], bf1[u]);
        }

        if (has_next) {
            const int nxt = cur ^ 1;
            unsigned* Asn = AsBase + nxt * GEMM_BUF;
            unsigned* Bsn = BsBase + nxt * GEMM_BUF;
            Asn[(a_cb + 0) * GSTR + a_row] = f2tf32(pa0.x);
            Asn[(a_cb + 1) * GSTR + a_row] = f2tf32(pa0.y);
            Asn[(a_cb + 2) * GSTR + a_row] = f2tf32(pa0.z);
            Asn[(a_cb + 3) * GSTR + a_row] = f2tf32(pa0.w);
            Asn[(a_cb + 4) * GSTR + a_row] = f2tf32(pa1.x);
            Asn[(a_cb + 5) * GSTR + a_row] = f2tf32(pa1.y);
            Asn[(a_cb + 6) * GSTR + a_row] = f2tf32(pa1.z);
            Asn[(a_cb + 7) * GSTR + a_row] = f2tf32(pa1.w);
            uint4 bv;
            bv.x = f2tf32(pb0.x); bv.y = f2tf32(pb0.y);
            bv.z = f2tf32(pb0.z); bv.w = f2tf32(pb0.w);
            *(uint4*)(&Bsn[b_row * GSTR + b_col]) = bv;
            bv.x = f2tf32(pb1.x); bv.y = f2tf32(pb1.y);
            bv.z = f2tf32(pb1.z); bv.w = f2tf32(pb1.w);
            *(uint4*)(&Bsn[(b_row + 8) * GSTR + b_col]) = bv;
            cur = nxt;
            __syncthreads();
        }
    }

    // ---- epilogue: alpha * (acc + bias) ----
    #pragma unroll
    for (int t = 0; t < 4; t++) {
        const int row0 = by * GBM + mb + t * 16 + gid;
        #pragma unroll
        for (int u = 0; u < 4; u++) {
            const int col = bx * GBN + nb + u * 8 + tg * 2;
            const float2 bv = *(const float2*)(bias + col);
            float2 c0, c1;
            c0.x = alpha * (acc[t][u][0] + bv.x);
            c0.y = alpha * (acc[t][u][1] + bv.y);
            c1.x = alpha * (acc[t][u][2] + bv.x);
            c1.y = alpha * (acc[t][u][3] + bv.y);
            *(float2*)(C + (size_t)row0 * DIM + col)       = c0;
            *(float2*)(C + (size_t)(row0 + 8) * DIM + col) = c1;
        }
    }
}

// ---------------------------------------------------------------------------
// Flash attention v3: tf32 tensor-core MMAs + FMA-pipe exp (no MUFU).
// (unchanged from R9 — GEMM is this round's isolated variable)
//
// softmax(s)*g / sum(softmax(s)*g) == 2^((s-m)log2e)*g / sum(...): gauss
// weight and mask fold into online-softmax weights.
//
// Block: 128 queries x one head, 256 threads = 8 warps.
// Warp w owns query rows [w*16, w*16+16) and ALL 64 keys of the tile;
// softmax rows never cross warps (2 shfl_xor; P consumed by same warp).
// ---------------------------------------------------------------------------
#define FBQ   128
#define FBK   64
#define FQSTR 136
#define FKSTR 72
#define FPSTR 72

#define FQS_OFF 0                                   // Qs: 64*136 = 8704
#define FKS_OFF (FQS_OFF + D_HEAD * FQSTR)          // Ks: 64*72  = 4608
#define FVS_OFF (FKS_OFF + FBK * FKSTR)             // Vs: 64*72  = 4608
#define FPS_OFF (FVS_OFF + FBK * FKSTR)             // Ps: 128*72 = 9216
#define FGS_OFF (FPS_OFF + FBQ * FPSTR)             // Gs: 64
#define FSMEM_WORDS (FGS_OFF + FBK)                 // 27200
#define FSMEM_BYTES (FSMEM_WORDS * 4)               // 108800

__global__ __launch_bounds__(256, 2) void flash_attn3_kernel(
    const int* __restrict__ mask, const float* __restrict__ gauss)
{
    extern __shared__ unsigned fsm[];
    unsigned* const Qs = fsm + FQS_OFF;
    unsigned* const Ks = fsm + FKS_OFF;
    unsigned* const Vs = fsm + FVS_OFF;
    unsigned* const Ps = fsm + FPS_OFF;
    float*    const Gs = (float*)(fsm + FGS_OFF);

    const int tid  = threadIdx.x;
    const int lane = tid & 31;
    const int wid  = tid >> 5;        // 0..7
    const int gid  = lane >> 2;       // 0..7
    const int tg   = lane & 3;        // 0..3
    const int mb   = wid * 16;        // warp's query-row base

    const int b     = blockIdx.z;
    const int h     = blockIdx.y;
    const int qbase = blockIdx.x * FBQ;

    // ---- load Q block transposed into Qs[d][q] as tf32 (once) ----
    {
        const float* qg = g_q + ((size_t)(b * SEQ + qbase)) * DIM + h * D_HEAD;
        #pragma unroll
        for (int c = 0; c < 8; c++) {
            int flat = (c * 256 + tid) * 4;       // 8192 floats
            int qr = flat >> 6;                    // 0..127
            int d  = flat & 63;
            float4 v = *(const float4*)(qg + (size_t)qr * DIM + d);
            Qs[(d + 0) * FQSTR + qr] = f2tf32(v.x);
            Qs[(d + 1) * FQSTR + qr] = f2tf32(v.y);
            Qs[(d + 2) * FQSTR + qr] = f2tf32(v.z);
            Qs[(d + 3) * FQSTR + qr] = f2tf32(v.w);
        }
    }

    float m_run[2], l_run[2];
    float acc_o[8][4];
    m_run[0] = m_run[1] = -1e30f;
    l_run[0] = l_run[1] = 0.f;
    #pragma unroll
    for (int u = 0; u < 8; u++)
        #pragma unroll
        for (int r = 0; r < 4; r++) acc_o[u][r] = 0.f;

    for (int kt = 0; kt < SEQ; kt += FBK) {
        __syncthreads();   // Q ready (1st iter) / all warps done with prev K,V

        // ---- load K, V natural (tf32), Gs ----
        {
            const float* kg = g_k + ((size_t)(b * SEQ + kt)) * DIM + h * D_HEAD;
            const float* vg = g_v + ((size_t)(b * SEQ + kt)) * DIM + h * D_HEAD;
            #pragma unroll
            for (int c = 0; c < 4; c++) {
                int flat = (c * 256 + tid) * 4;    // 4096 floats each
                int kr = flat >> 6;                 // 0..63
                int d  = flat & 63;
                float4 kv = *(const float4*)(kg + (size_t)kr * DIM + d);
                float4 vv = *(const float4*)(vg + (size_t)kr * DIM + d);
                uint4 ku, vu;
                ku.x = f2tf32(kv.x); ku.y = f2tf32(kv.y);
                ku.z = f2tf32(kv.z); ku.w = f2tf32(kv.w);
                vu.x = f2tf32(vv.x); vu.y = f2tf32(vv.y);
                vu.z = f2tf32(vv.z); vu.w = f2tf32(vv.w);
                *(uint4*)(Ks + kr * FKSTR + d) = ku;
                *(uint4*)(Vs + kr * FKSTR + d) = vu;
            }
            if (tid < FBK) {
                int kk = kt + tid;
                float g = gauss[b * SEQ + kk] + 1e-10f;
                Gs[tid] = (mask[b * SEQ + kk] == 0) ? 0.f : g;
            }
        }
        __syncthreads();   // tile visible

        // ---- S = Q · K^T : warp tile 16(q) x 64(k), K-dim = 64 ----
        float acc_s[8][4];
        #pragma unroll
        for (int u = 0; u < 8; u++)
            #pragma unroll
            for (int r = 0; r < 4; r++) acc_s[u][r] = 0.f;

        #pragma unroll
        for (int kb = 0; kb < D_HEAD; kb += 8) {
            unsigned af0, af1, af2, af3, bf0[8], bf1[8];
            af0 = Qs[(kb + tg    ) * FQSTR + mb + gid];
            af1 = Qs[(kb + tg    ) * FQSTR + mb + gid + 8];
            af2 = Qs[(kb + tg + 4) * FQSTR + mb + gid];
            af3 = Qs[(kb + tg + 4) * FQSTR + mb + gid + 8];
            #pragma unroll
            for (int u = 0; u < 8; u++) {
                const int n0 = u * 8 + gid;        // key index
                bf0[u] = Ks[n0 * FKSTR + kb + tg    ];   // B[k][n] = K[n][k]
                bf1[u] = Ks[n0 * FKSTR + kb + tg + 4];
            }
            #pragma unroll
            for (int u = 0; u < 8; u++)
                mma_tf32(acc_s[u], af0, af1, af2, af3, bf0[u], bf1[u]);
        }

        // ---- online softmax (FMA-pipe exp), gauss/mask folded ----
        float g2v[8][2];
        #pragma unroll
        for (int u = 0; u < 8; u++) {
            float2 gg = *(const float2*)(Gs + u * 8 + tg * 2);
            g2v[u][0] = gg.x; g2v[u][1] = gg.y;
        }

        float osc[2];
        #pragma unroll
        for (int rh = 0; rh < 2; rh++) {
            float lm = -1e30f;
            #pragma unroll
            for (int u = 0; u < 8; u++) {
                float e0 = (g2v[u][0] > 0.f) ? acc_s[u][rh*2+0] : -1e30f;
                float e1 = (g2v[u][1] > 0.f) ? acc_s[u][rh*2+1] : -1e30f;
                lm = fmaxf(lm, fmaxf(e0, e1));
            }
            lm = fmaxf(lm, __shfl_xor_sync(0xffffffffu, lm, 1));
            lm = fmaxf(lm, __shfl_xor_sync(0xffffffffu, lm, 2));

            const float mnew = fmaxf(m_run[rh], lm);
            const float scl  = fast_exp2((m_run[rh] - mnew) * LOG2E);
            const float mlg  = mnew * LOG2E;
            float rs = 0.f;
            #pragma unroll
            for (int u = 0; u < 8; u++) {
                #pragma unroll
                for (int c = 0; c < 2; c++) {
                    float x = fmaf(acc_s[u][rh*2+c], LOG2E, -mlg);
                    float p = fast_exp2(x) * g2v[u][c];   // masked: g=0 -> p=0
                    acc_s[u][rh*2+c] = p;
                    rs += p;
                }
            }
            rs += __shfl_xor_sync(0xffffffffu, rs, 1);
            rs += __shfl_xor_sync(0xffffffffu, rs, 2);

            l_run[rh] = l_run[rh] * scl + rs;
            m_run[rh] = mnew;
            osc[rh]   = scl;
        }
        #pragma unroll
        for (int u = 0; u < 8; u++)
            #pragma unroll
            for (int r = 0; r < 4; r++) acc_o[u][r] *= osc[r >> 1];

        // ---- stage P (tf32) to Ps[q][key]; same warp consumes it ----
        #pragma unroll
        for (int rh = 0; rh < 2; rh++) {
            const int qrow = mb + gid + rh * 8;
            #pragma unroll
            for (int u = 0; u < 8; u++) {
                uint2 pv;
                pv.x = f2tf32(acc_s[u][rh*2+0]);
                pv.y = f2tf32(acc_s[u][rh*2+1]);
                *(uint2*)(Ps + qrow * FPSTR + u * 8 + tg * 2) = pv;
            }
        }
        __syncwarp();

        // ---- O += P · V : warp tile 16(q) x 64(d), K-dim = 64 keys ----
        #pragma unroll
        for (int kb = 0; kb < FBK; kb += 8) {
            unsigned af0, af1, af2, af3, bf0[8], bf1[8];
            af0 = Ps[(mb + gid    ) * FPSTR + kb + tg    ];
            af1 = Ps[(mb + gid + 8) * FPSTR + kb + tg    ];
            af2 = Ps[(mb + gid    ) * FPSTR + kb + tg + 4];
            af3 = Ps[(mb + gid + 8) * FPSTR + kb + tg + 4];
            #pragma unroll
            for (int u = 0; u < 8; u++) {
                const int n0 = u * 8 + gid;        // head-dim index
                bf0[u] = Vs[(kb + tg    ) * FKSTR + n0];
                bf1[u] = Vs[(kb + tg + 4) * FKSTR + n0];
            }
            #pragma unroll
            for (int u = 0; u < 8; u++)
                mma_tf32(acc_o[u], af0, af1, af2, af3, bf0[u], bf1[u]);
        }
    }

    // ---- epilogue: normalize and store ----
    #pragma unroll
    for (int rh = 0; rh < 2; rh++) {
        const float inv = 1.f / l_run[rh];
        const int qrow = qbase + mb + gid + rh * 8;
        float* op = g_ctx + ((size_t)(b * SEQ + qrow)) * DIM + h * D_HEAD;
        #pragma unroll
        for (int u = 0; u < 8; u++) {
            float2 ov;
            ov.x = acc_o[u][rh*2+0] * inv;
            ov.y = acc_o[u][rh*2+1] * inv;
            *(float2*)(op + u * 8 + tg * 2) = ov;
        }
    }
}

// ---------------------------------------------------------------------------
// Launch
// inputs: 0=query 1=key 2=value 3=mask 4=gauss_weight
//         5=Wq 6=bq 7=Wk 8=bk 9=Wv 10=bv 11=Wo 12=bo
// ---------------------------------------------------------------------------
extern "C" void kernel_launch(void* const* d_in, const int* in_sizes, int n_in,
                              void* d_out, int out_size)
{
    const float* query = (const float*)d_in[0];
    const float* key   = (const float*)d_in[1];
    const float* value = (const float*)d_in[2];
    const int*   mask  = (const int*)  d_in[3];
    const float* gauss = (const float*)d_in[4];
    const float* Wq = (const float*)d_in[5];
    const float* bq = (const float*)d_in[6];
    const float* Wk = (const float*)d_in[7];
    const float* bk = (const float*)d_in[8];
    const float* Wv = (const float*)d_in[9];
    const float* bv = (const float*)d_in[10];
    const float* Wo = (const float*)d_in[11];
    const float* bo = (const float*)d_in[12];
    float* out = (float*)d_out;

    float *pq, *pk, *pv, *pctx;
    cudaGetSymbolAddress((void**)&pq,   g_q);
    cudaGetSymbolAddress((void**)&pk,   g_k);
    cudaGetSymbolAddress((void**)&pv,   g_v);
    cudaGetSymbolAddress((void**)&pctx, g_ctx);

    // allow >48KB dynamic smem (idempotent host calls, not stream ops ->
    // safe under graph capture)
    cudaFuncSetAttribute(tf32_gemm_kernel,
                         cudaFuncAttributeMaxDynamicSharedMemorySize,
                         GEMM_SMEM_BYTES);
    cudaFuncSetAttribute(flash_attn3_kernel,
                         cudaFuncAttributeMaxDynamicSharedMemorySize,
                         FSMEM_BYTES);

    dim3 ggrid(DIM / GBN, MROWS / GBM);   // (8, 32) = 256 blocks, 2/SM
    const float qscale = 1.0f / 8.0f;     // 1/sqrt(D_HEAD)

    tf32_gemm_kernel<<<ggrid, 256, GEMM_SMEM_BYTES>>>(query, Wq, bq, pq, qscale);
    tf32_gemm_kernel<<<ggrid, 256, GEMM_SMEM_BYTES>>>(key,   Wk, bk, pk, 1.0f);
    tf32_gemm_kernel<<<ggrid, 256, GEMM_SMEM_BYTES>>>(value, Wv, bv, pv, 1.0f);

    dim3 agrid(SEQ / FBQ, N_HEADS, BS);   // (8, 16, 4)
    flash_attn3_kernel<<<agrid, 256, FSMEM_BYTES>>>(mask, gauss);

    tf32_gemm_kernel<<<ggrid, 256, GEMM_SMEM_BYTES>>>(pctx, Wo, bo, out, 1.0f);
}

// round 11
// speedup vs baseline: 1.0962x; 1.0962x over previous
#include <cuda_runtime.h>
#include <cuda_bf16.h>
#include <math.h>

// Problem constants
#define BS      4
#define SEQ     1024
#define DIM     1024
#define N_HEADS 16
#define D_HEAD  64
#define MROWS   (BS * SEQ)      // 4096

// ---------------------------------------------------------------------------
// Scratch (static device globals; no runtime allocation allowed)
// ---------------------------------------------------------------------------
__device__ float g_q  [MROWS * DIM];
__device__ float g_k  [MROWS * DIM];
__device__ float g_v  [MROWS * DIM];
__device__ float g_ctx[MROWS * DIM];

// ---------------------------------------------------------------------------
// Common tf32 helpers
// ---------------------------------------------------------------------------
__device__ __forceinline__ unsigned f2tf32(float f) {
    unsigned u;
    asm("cvt.rna.tf32.f32 %0, %1;" : "=r"(u) : "f"(f));
    return u;
}

__device__ __forceinline__ void mma_tf32(float c[4],
    unsigned a0, unsigned a1, unsigned a2, unsigned a3,
    unsigned b0, unsigned b1)
{
    asm volatile(
        "mma.sync.aligned.m16n8k8.row.col.f32.tf32.tf32.f32 "
        "{%0,%1,%2,%3}, {%4,%5,%6,%7}, {%8,%9}, {%0,%1,%2,%3};"
        : "+f"(c[0]), "+f"(c[1]), "+f"(c[2]), "+f"(c[3])
        : "r"(a0), "r"(a1), "r"(a2), "r"(a3), "r"(b0), "r"(b1));
}

// Fast 2^x on the FMA/ALU pipes (no MUFU). Valid for x in [-100, 100];
// clamps outside. Rel err ~3e-6 (degree-5 Taylor on f in [-0.5, 0.5]).
#define LOG2E 1.4426950408889634f
__device__ __forceinline__ float fast_exp2(float x) {
    x = fminf(fmaxf(x, -100.0f), 100.0f);
    float z = x + 12582912.0f;                 // 1.5*2^23: round-to-nearest int
    int   n = __float_as_int(z) - 0x4B400000;  // n = round(x)
    float f = x - (z - 12582912.0f);           // f in [-0.5, 0.5]
    float p =            1.3333558e-3f;
    p = fmaf(p, f, 9.6181291e-3f);
    p = fmaf(p, f, 5.5504109e-2f);
    p = fmaf(p, f, 2.4022650e-1f);
    p = fmaf(p, f, 6.9314718e-1f);
    p = fmaf(p, f, 1.0f);                      // p in [0.707, 1.415)
    return __int_as_float(__float_as_int(p) + (n << 23));
}

// ---------------------------------------------------------------------------
// TF32 tensor-core GEMM: C = alpha * (A @ B + bias)   (R9 version — best)
// Block tile 256x128, BK=16, 512 threads = 16 warps (4x4), warp tile 64x32.
// Grid (8, 16) = 128 blocks -> single wave. Smem: As[2][16][264], Bs[2][16][136]
// ---------------------------------------------------------------------------
#define GBM 256
#define GBN 128
#define GBK 16
#define ASTR 264
#define BSTR 136
#define GEMM_A_BUF (GBK * ASTR)
#define GEMM_B_BUF (GBK * BSTR)
#define GEMM_SMEM_WORDS (2 * GEMM_A_BUF + 2 * GEMM_B_BUF)
#define GEMM_SMEM_BYTES (GEMM_SMEM_WORDS * 4)       // 51200

__global__ __launch_bounds__(512, 1) void tf32_gemm_kernel(
    const float* __restrict__ A, const float* __restrict__ B,
    const float* __restrict__ bias, float* __restrict__ C,
    float alpha)
{
    extern __shared__ unsigned gsm[];
    unsigned* const AsBase = gsm;
    unsigned* const BsBase = gsm + 2 * GEMM_A_BUF;

    const int tid  = threadIdx.x;
    const int lane = tid & 31;
    const int wid  = tid >> 5;
    const int gid  = lane >> 2;
    const int tg   = lane & 3;

    const int warp_m = wid & 3;
    const int warp_n = wid >> 2;
    const int mb = warp_m * 64;
    const int nb = warp_n * 32;

    const int bx = blockIdx.x;
    const int by = blockIdx.y;

    const float* Ab = A + (size_t)by * GBM * DIM;
    const float* Bb = B + (size_t)bx * GBN;

    const int a_row = tid & 255;
    const int a_cb  = (tid >> 8) * 8;
    const int b_row = tid >> 5;
    const int b_col = (tid & 31) * 4;

    float acc[4][4][4];
    #pragma unroll
    for (int t = 0; t < 4; t++)
        #pragma unroll
        for (int u = 0; u < 4; u++)
            #pragma unroll
            for (int r = 0; r < 4; r++)
                acc[t][u][r] = 0.f;

    float4 pa0, pa1, pb0;

    pa0 = *(const float4*)(Ab + (size_t)a_row * DIM + a_cb);
    pa1 = *(const float4*)(Ab + (size_t)a_row * DIM + a_cb + 4);
    pb0 = *(const float4*)(Bb + (size_t)b_row * DIM + b_col);
    {
        unsigned* As0 = AsBase;
        unsigned* Bs0 = BsBase;
        As0[(a_cb + 0) * ASTR + a_row] = f2tf32(pa0.x);
        As0[(a_cb + 1) * ASTR + a_row] = f2tf32(pa0.y);
        As0[(a_cb + 2) * ASTR + a_row] = f2tf32(pa0.z);
        As0[(a_cb + 3) * ASTR + a_row] = f2tf32(pa0.w);
        As0[(a_cb + 4) * ASTR + a_row] = f2tf32(pa1.x);
        As0[(a_cb + 5) * ASTR + a_row] = f2tf32(pa1.y);
        As0[(a_cb + 6) * ASTR + a_row] = f2tf32(pa1.z);
        As0[(a_cb + 7) * ASTR + a_row] = f2tf32(pa1.w);
        uint4 bv;
        bv.x = f2tf32(pb0.x); bv.y = f2tf32(pb0.y);
        bv.z = f2tf32(pb0.z); bv.w = f2tf32(pb0.w);
        *(uint4*)(&Bs0[b_row * BSTR + b_col]) = bv;
    }
    __syncthreads();

    const int NT = DIM / GBK;
    int cur = 0;
    for (int t0 = 0; t0 < NT; t0++) {
        const bool has_next = (t0 + 1) < NT;
        if (has_next) {
            const int kn = (t0 + 1) * GBK;
            pa0 = *(const float4*)(Ab + (size_t)a_row * DIM + kn + a_cb);
            pa1 = *(const float4*)(Ab + (size_t)a_row * DIM + kn + a_cb + 4);
            pb0 = *(const float4*)(Bb + (size_t)(kn + b_row) * DIM + b_col);
        }

        const unsigned* Asc = AsBase + cur * GEMM_A_BUF;
        const unsigned* Bsc = BsBase + cur * GEMM_B_BUF;
        #pragma unroll
        for (int kb = 0; kb < GBK; kb += 8) {
            unsigned af0[4], af1[4], af2[4], af3[4], bf0[4], bf1[4];
            #pragma unroll
            for (int t = 0; t < 4; t++) {
                const int m0 = mb + t * 16 + gid;
                af0[t] = Asc[(kb + tg    ) * ASTR + m0];
                af1[t] = Asc[(kb + tg    ) * ASTR + m0 + 8];
                af2[t] = Asc[(kb + tg + 4) * ASTR + m0];
                af3[t] = Asc[(kb + tg + 4) * ASTR + m0 + 8];
            }
            #pragma unroll
            for (int u = 0; u < 4; u++) {
                const int n0 = nb + u * 8 + gid;
                bf0[u] = Bsc[(kb + tg    ) * BSTR + n0];
                bf1[u] = Bsc[(kb + tg + 4) * BSTR + n0];
            }
            #pragma unroll
            for (int t = 0; t < 4; t++)
                #pragma unroll
                for (int u = 0; u < 4; u++)
                    mma_tf32(acc[t][u], af0[t], af1[t], af2[t], af3[t],
                             bf0[u], bf1[u]);
        }

        if (has_next) {
            const int nxt = cur ^ 1;
            unsigned* Asn = AsBase + nxt * GEMM_A_BUF;
            unsigned* Bsn = BsBase + nxt * GEMM_B_BUF;
            Asn[(a_cb + 0) * ASTR + a_row] = f2tf32(pa0.x);
            Asn[(a_cb + 1) * ASTR + a_row] = f2tf32(pa0.y);
            Asn[(a_cb + 2) * ASTR + a_row] = f2tf32(pa0.z);
            Asn[(a_cb + 3) * ASTR + a_row] = f2tf32(pa0.w);
            Asn[(a_cb + 4) * ASTR + a_row] = f2tf32(pa1.x);
            Asn[(a_cb + 5) * ASTR + a_row] = f2tf32(pa1.y);
            Asn[(a_cb + 6) * ASTR + a_row] = f2tf32(pa1.z);
            Asn[(a_cb + 7) * ASTR + a_row] = f2tf32(pa1.w);
            uint4 bv;
            bv.x = f2tf32(pb0.x); bv.y = f2tf32(pb0.y);
            bv.z = f2tf32(pb0.z); bv.w = f2tf32(pb0.w);
            *(uint4*)(&Bsn[b_row * BSTR + b_col]) = bv;
            cur = nxt;
            __syncthreads();
        }
    }

    #pragma unroll
    for (int t = 0; t < 4; t++) {
        const int row0 = by * GBM + mb + t * 16 + gid;
        #pragma unroll
        for (int u = 0; u < 4; u++) {
            const int col = bx * GBN + nb + u * 8 + tg * 2;
            const float2 bv = *(const float2*)(bias + col);
            float2 c0, c1;
            c0.x = alpha * (acc[t][u][0] + bv.x);
            c0.y = alpha * (acc[t][u][1] + bv.y);
            c1.x = alpha * (acc[t][u][2] + bv.x);
            c1.y = alpha * (acc[t][u][3] + bv.y);
            *(float2*)(C + (size_t)row0 * DIM + col)       = c0;
            *(float2*)(C + (size_t)(row0 + 8) * DIM + col) = c1;
        }
    }
}

// ---------------------------------------------------------------------------
// Flash attention v3.1: tf32 MMAs + FMA-pipe exp, bank-conflict-free strides.
//
// Bank math (banks = addr mod 32, lanes indexed by gid=lane>>2, tg=lane&3):
//   K  B-frag loads: addr = (u*8+gid)*KSTR_K + kb+tg -> banks KSTR_K*gid + tg
//       -> KSTR_K must be == 4 (mod 32): KSTR_K = 68   (72 was 2-way conflicted)
//   V  B-frag loads: addr = (kb+tg)*KSTR_V + u*8+gid -> banks KSTR_V*tg + gid
//       -> KSTR_V must be == 8 (mod 32): KSTR_V = 72   (already correct)
//   P  A-frag loads: addr = (mb+gid)*FPSTR + kb+tg   -> banks FPSTR*gid + tg
//       -> FPSTR == 4 (mod 32): FPSTR = 68             (72 was 2-way conflicted)
//   Q  A-frag loads: addr = (kb+tg)*FQSTR + mb+gid   -> banks FQSTR*tg + gid
//       -> FQSTR == 8 (mod 32): FQSTR = 136            (already correct)
// ---------------------------------------------------------------------------
#define FBQ    128
#define FBK    64
#define FQSTR  136
#define KSTR_K 68
#define KSTR_V 72
#define FPSTR  68

#define FQS_OFF 0                                   // Qs: 64*136 = 8704
#define FKS_OFF (FQS_OFF + D_HEAD * FQSTR)          // Ks: 64*68  = 4352
#define FVS_OFF (FKS_OFF + FBK * KSTR_K)            // Vs: 64*72  = 4608
#define FPS_OFF (FVS_OFF + FBK * KSTR_V)            // Ps: 128*68 = 8704
#define FGS_OFF (FPS_OFF + FBQ * FPSTR)             // Gs: 64
#define FSMEM_WORDS (FGS_OFF + FBK)                 // 26432
#define FSMEM_BYTES (FSMEM_WORDS * 4)               // 105728

__global__ __launch_bounds__(256, 2) void flash_attn3_kernel(
    const int* __restrict__ mask, const float* __restrict__ gauss)
{
    extern __shared__ unsigned fsm[];
    unsigned* const Qs = fsm + FQS_OFF;
    unsigned* const Ks = fsm + FKS_OFF;
    unsigned* const Vs = fsm + FVS_OFF;
    unsigned* const Ps = fsm + FPS_OFF;
    float*    const Gs = (float*)(fsm + FGS_OFF);

    const int tid  = threadIdx.x;
    const int lane = tid & 31;
    const int wid  = tid >> 5;        // 0..7
    const int gid  = lane >> 2;       // 0..7
    const int tg   = lane & 3;        // 0..3
    const int mb   = wid * 16;        // warp's query-row base

    const int b     = blockIdx.z;
    const int h     = blockIdx.y;
    const int qbase = blockIdx.x * FBQ;

    // ---- load Q block transposed into Qs[d][q] as tf32 (once) ----
    {
        const float* qg = g_q + ((size_t)(b * SEQ + qbase)) * DIM + h * D_HEAD;
        #pragma unroll
        for (int c = 0; c < 8; c++) {
            int flat = (c * 256 + tid) * 4;       // 8192 floats
            int qr = flat >> 6;                    // 0..127
            int d  = flat & 63;
            float4 v = *(const float4*)(qg + (size_t)qr * DIM + d);
            Qs[(d + 0) * FQSTR + qr] = f2tf32(v.x);
            Qs[(d + 1) * FQSTR + qr] = f2tf32(v.y);
            Qs[(d + 2) * FQSTR + qr] = f2tf32(v.z);
            Qs[(d + 3) * FQSTR + qr] = f2tf32(v.w);
        }
    }

    float m_run[2], l_run[2];
    float acc_o[8][4];
    m_run[0] = m_run[1] = -1e30f;
    l_run[0] = l_run[1] = 0.f;
    #pragma unroll
    for (int u = 0; u < 8; u++)
        #pragma unroll
        for (int r = 0; r < 4; r++) acc_o[u][r] = 0.f;

    for (int kt = 0; kt < SEQ; kt += FBK) {
        __syncthreads();   // Q ready (1st iter) / all warps done with prev K,V

        // ---- load K, V natural (tf32), Gs ----
        {
            const float* kg = g_k + ((size_t)(b * SEQ + kt)) * DIM + h * D_HEAD;
            const float* vg = g_v + ((size_t)(b * SEQ + kt)) * DIM + h * D_HEAD;
            #pragma unroll
            for (int c = 0; c < 4; c++) {
                int flat = (c * 256 + tid) * 4;    // 4096 floats each
                int kr = flat >> 6;                 // 0..63
                int d  = flat & 63;
                float4 kv = *(const float4*)(kg + (size_t)kr * DIM + d);
                float4 vv = *(const float4*)(vg + (size_t)kr * DIM + d);
                uint4 ku, vu;
                ku.x = f2tf32(kv.x); ku.y = f2tf32(kv.y);
                ku.z = f2tf32(kv.z); ku.w = f2tf32(kv.w);
                vu.x = f2tf32(vv.x); vu.y = f2tf32(vv.y);
                vu.z = f2tf32(vv.z); vu.w = f2tf32(vv.w);
                *(uint4*)(Ks + kr * KSTR_K + d) = ku;
                *(uint4*)(Vs + kr * KSTR_V + d) = vu;
            }
            if (tid < FBK) {
                int kk = kt + tid;
                float g = gauss[b * SEQ + kk] + 1e-10f;
                Gs[tid] = (mask[b * SEQ + kk] == 0) ? 0.f : g;
            }
        }
        __syncthreads();   // tile visible

        // ---- S = Q · K^T : warp tile 16(q) x 64(k), K-dim = 64 ----
        float acc_s[8][4];
        #pragma unroll
        for (int u = 0; u < 8; u++)
            #pragma unroll
            for (int r = 0; r < 4; r++) acc_s[u][r] = 0.f;

        #pragma unroll
        for (int kb = 0; kb < D_HEAD; kb += 8) {
            unsigned af0, af1, af2, af3, bf0[8], bf1[8];
            af0 = Qs[(kb + tg    ) * FQSTR + mb + gid];
            af1 = Qs[(kb + tg    ) * FQSTR + mb + gid + 8];
            af2 = Qs[(kb + tg + 4) * FQSTR + mb + gid];
            af3 = Qs[(kb + tg + 4) * FQSTR + mb + gid + 8];
            #pragma unroll
            for (int u = 0; u < 8; u++) {
                const int n0 = u * 8 + gid;        // key index
                bf0[u] = Ks[n0 * KSTR_K + kb + tg    ];  // B[k][n] = K[n][k]
                bf1[u] = Ks[n0 * KSTR_K + kb + tg + 4];
            }
            #pragma unroll
            for (int u = 0; u < 8; u++)
                mma_tf32(acc_s[u], af0, af1, af2, af3, bf0[u], bf1[u]);
        }

        // ---- online softmax (FMA-pipe exp), gauss/mask folded ----
        float g2v[8][2];
        #pragma unroll
        for (int u = 0; u < 8; u++) {
            float2 gg = *(const float2*)(Gs + u * 8 + tg * 2);
            g2v[u][0] = gg.x; g2v[u][1] = gg.y;
        }

        float osc[2];
        #pragma unroll
        for (int rh = 0; rh < 2; rh++) {
            float lm = -1e30f;
            #pragma unroll
            for (int u = 0; u < 8; u++) {
                float e0 = (g2v[u][0] > 0.f) ? acc_s[u][rh*2+0] : -1e30f;
                float e1 = (g2v[u][1] > 0.f) ? acc_s[u][rh*2+1] : -1e30f;
                lm = fmaxf(lm, fmaxf(e0, e1));
            }
            lm = fmaxf(lm, __shfl_xor_sync(0xffffffffu, lm, 1));
            lm = fmaxf(lm, __shfl_xor_sync(0xffffffffu, lm, 2));

            const float mnew = fmaxf(m_run[rh], lm);
            const float scl  = fast_exp2((m_run[rh] - mnew) * LOG2E);
            const float mlg  = mnew * LOG2E;
            float rs = 0.f;
            #pragma unroll
            for (int u = 0; u < 8; u++) {
                #pragma unroll
                for (int c = 0; c < 2; c++) {
                    float x = fmaf(acc_s[u][rh*2+c], LOG2E, -mlg);
                    float p = fast_exp2(x) * g2v[u][c];   // masked: g=0 -> p=0
                    acc_s[u][rh*2+c] = p;
                    rs += p;
                }
            }
            rs += __shfl_xor_sync(0xffffffffu, rs, 1);
            rs += __shfl_xor_sync(0xffffffffu, rs, 2);

            l_run[rh] = l_run[rh] * scl + rs;
            m_run[rh] = mnew;
            osc[rh]   = scl;
        }
        #pragma unroll
        for (int u = 0; u < 8; u++)
            #pragma unroll
            for (int r = 0; r < 4; r++) acc_o[u][r] *= osc[r >> 1];

        // ---- stage P (tf32) to Ps[q][key]; same warp consumes it ----
        #pragma unroll
        for (int rh = 0; rh < 2; rh++) {
            const int qrow = mb + gid + rh * 8;
            #pragma unroll
            for (int u = 0; u < 8; u++) {
                uint2 pv;
                pv.x = f2tf32(acc_s[u][rh*2+0]);
                pv.y = f2tf32(acc_s[u][rh*2+1]);
                *(uint2*)(Ps + qrow * FPSTR + u * 8 + tg * 2) = pv;
            }
        }
        __syncwarp();

        // ---- O += P · V : warp tile 16(q) x 64(d), K-dim = 64 keys ----
        #pragma unroll
        for (int kb = 0; kb < FBK; kb += 8) {
            unsigned af0, af1, af2, af3, bf0[8], bf1[8];
            af0 = Ps[(mb + gid    ) * FPSTR + kb + tg    ];
            af1 = Ps[(mb + gid + 8) * FPSTR + kb + tg    ];
            af2 = Ps[(mb + gid    ) * FPSTR + kb + tg + 4];
            af3 = Ps[(mb + gid + 8) * FPSTR + kb + tg + 4];
            #pragma unroll
            for (int u = 0; u < 8; u++) {
                const int n0 = u * 8 + gid;        // head-dim index
                bf0[u] = Vs[(kb + tg    ) * KSTR_V + n0];
                bf1[u] = Vs[(kb + tg + 4) * KSTR_V + n0];
            }
            #pragma unroll
            for (int u = 0; u < 8; u++)
                mma_tf32(acc_o[u], af0, af1, af2, af3, bf0[u], bf1[u]);
        }
    }

    // ---- epilogue: normalize and store ----
    #pragma unroll
    for (int rh = 0; rh < 2; rh++) {
        const float inv = 1.f / l_run[rh];
        const int qrow = qbase + mb + gid + rh * 8;
        float* op = g_ctx + ((size_t)(b * SEQ + qrow)) * DIM + h * D_HEAD;
        #pragma unroll
        for (int u = 0; u < 8; u++) {
            float2 ov;
            ov.x = acc_o[u][rh*2+0] * inv;
            ov.y = acc_o[u][rh*2+1] * inv;
            *(float2*)(op + u * 8 + tg * 2) = ov;
        }
    }
}

// ---------------------------------------------------------------------------
// Launch
// inputs: 0=query 1=key 2=value 3=mask 4=gauss_weight
//         5=Wq 6=bq 7=Wk 8=bk 9=Wv 10=bv 11=Wo 12=bo
// ---------------------------------------------------------------------------
extern "C" void kernel_launch(void* const* d_in, const int* in_sizes, int n_in,
                              void* d_out, int out_size)
{
    const float* query = (const float*)d_in[0];
    const float* key   = (const float*)d_in[1];
    const float* value = (const float*)d_in[2];
    const int*   mask  = (const int*)  d_in[3];
    const float* gauss = (const float*)d_in[4];
    const float* Wq = (const float*)d_in[5];
    const float* bq = (const float*)d_in[6];
    const float* Wk = (const float*)d_in[7];
    const float* bk = (const float*)d_in[8];
    const float* Wv = (const float*)d_in[9];
    const float* bv = (const float*)d_in[10];
    const float* Wo = (const float*)d_in[11];
    const float* bo = (const float*)d_in[12];
    float* out = (float*)d_out;

    float *pq, *pk, *pv, *pctx;
    cudaGetSymbolAddress((void**)&pq,   g_q);
    cudaGetSymbolAddress((void**)&pk,   g_k);
    cudaGetSymbolAddress((void**)&pv,   g_v);
    cudaGetSymbolAddress((void**)&pctx, g_ctx);

    // allow >48KB dynamic smem (idempotent host calls, not stream ops ->
    // safe under graph capture)
    cudaFuncSetAttribute(tf32_gemm_kernel,
                         cudaFuncAttributeMaxDynamicSharedMemorySize,
                         GEMM_SMEM_BYTES);
    cudaFuncSetAttribute(flash_attn3_kernel,
                         cudaFuncAttributeMaxDynamicSharedMemorySize,
                         FSMEM_BYTES);

    dim3 ggrid(DIM / GBN, MROWS / GBM);   // (8, 16) = 128 blocks
    const float qscale = 1.0f / 8.0f;     // 1/sqrt(D_HEAD)

    tf32_gemm_kernel<<<ggrid, 512, GEMM_SMEM_BYTES>>>(query, Wq, bq, pq, qscale);
    tf32_gemm_kernel<<<ggrid, 512, GEMM_SMEM_BYTES>>>(key,   Wk, bk, pk, 1.0f);
    tf32_gemm_kernel<<<ggrid, 512, GEMM_SMEM_BYTES>>>(value, Wv, bv, pv, 1.0f);

    dim3 agrid(SEQ / FBQ, N_HEADS, BS);   // (8, 16, 4)
    flash_attn3_kernel<<<agrid, 256, FSMEM_BYTES>>>(mask, gauss);

    tf32_gemm_kernel<<<ggrid, 512, GEMM_SMEM_BYTES>>>(pctx, Wo, bo, out, 1.0f);
}

// round 12
// speedup vs baseline: 1.1194x; 1.0211x over previous
#include <cuda_runtime.h>
#include <cuda_bf16.h>
#include <math.h>

// Problem constants
#define BS      4
#define SEQ     1024
#define DIM     1024
#define N_HEADS 16
#define D_HEAD  64
#define MROWS   (BS * SEQ)      // 4096

// ---------------------------------------------------------------------------
// Scratch (static device globals; no runtime allocation allowed)
// ---------------------------------------------------------------------------
__device__ float g_q  [MROWS * DIM];
__device__ float g_k  [MROWS * DIM];
__device__ float g_v  [MROWS * DIM];
__device__ float g_ctx[MROWS * DIM];

// ---------------------------------------------------------------------------
// Common tf32 helpers
// ---------------------------------------------------------------------------
__device__ __forceinline__ unsigned f2tf32(float f) {
    unsigned u;
    asm("cvt.rna.tf32.f32 %0, %1;" : "=r"(u) : "f"(f));
    return u;
}

__device__ __forceinline__ void mma_tf32(float c[4],
    unsigned a0, unsigned a1, unsigned a2, unsigned a3,
    unsigned b0, unsigned b1)
{
    asm volatile(
        "mma.sync.aligned.m16n8k8.row.col.f32.tf32.tf32.f32 "
        "{%0,%1,%2,%3}, {%4,%5,%6,%7}, {%8,%9}, {%0,%1,%2,%3};"
        : "+f"(c[0]), "+f"(c[1]), "+f"(c[2]), "+f"(c[3])
        : "r"(a0), "r"(a1), "r"(a2), "r"(a3), "r"(b0), "r"(b1));
}

// Fast 2^x on the FMA/ALU pipes (no MUFU). Valid for x in [-100, 100];
// clamps outside. Rel err ~3e-6 (degree-5 Taylor on f in [-0.5, 0.5]).
#define LOG2E 1.4426950408889634f
__device__ __forceinline__ float fast_exp2(float x) {
    x = fminf(fmaxf(x, -100.0f), 100.0f);
    float z = x + 12582912.0f;                 // 1.5*2^23: round-to-nearest int
    int   n = __float_as_int(z) - 0x4B400000;  // n = round(x)
    float f = x - (z - 12582912.0f);           // f in [-0.5, 0.5]
    float p =            1.3333558e-3f;
    p = fmaf(p, f, 9.6181291e-3f);
    p = fmaf(p, f, 5.5504109e-2f);
    p = fmaf(p, f, 2.4022650e-1f);
    p = fmaf(p, f, 6.9314718e-1f);
    p = fmaf(p, f, 1.0f);                      // p in [0.707, 1.415)
    return __int_as_float(__float_as_int(p) + (n << 23));
}

// ---------------------------------------------------------------------------
// TF32 tensor-core GEMM: C = alpha * (A @ B + bias)   (R9 version — best)
// Block tile 256x128, BK=16, 512 threads = 16 warps (4x4), warp tile 64x32.
// Grid (8, 16) = 128 blocks -> single wave. Smem: As[2][16][264], Bs[2][16][136]
// ---------------------------------------------------------------------------
#define GBM 256
#define GBN 128
#define GBK 16
#define ASTR 264
#define BSTR 136
#define GEMM_A_BUF (GBK * ASTR)
#define GEMM_B_BUF (GBK * BSTR)
#define GEMM_SMEM_WORDS (2 * GEMM_A_BUF + 2 * GEMM_B_BUF)
#define GEMM_SMEM_BYTES (GEMM_SMEM_WORDS * 4)       // 51200

__global__ __launch_bounds__(512, 1) void tf32_gemm_kernel(
    const float* __restrict__ A, const float* __restrict__ B,
    const float* __restrict__ bias, float* __restrict__ C,
    float alpha)
{
    extern __shared__ unsigned gsm[];
    unsigned* const AsBase = gsm;
    unsigned* const BsBase = gsm + 2 * GEMM_A_BUF;

    const int tid  = threadIdx.x;
    const int lane = tid & 31;
    const int wid  = tid >> 5;
    const int gid  = lane >> 2;
    const int tg   = lane & 3;

    const int warp_m = wid & 3;
    const int warp_n = wid >> 2;
    const int mb = warp_m * 64;
    const int nb = warp_n * 32;

    const int bx = blockIdx.x;
    const int by = blockIdx.y;

    const float* Ab = A + (size_t)by * GBM * DIM;
    const float* Bb = B + (size_t)bx * GBN;

    const int a_row = tid & 255;
    const int a_cb  = (tid >> 8) * 8;
    const int b_row = tid >> 5;
    const int b_col = (tid & 31) * 4;

    float acc[4][4][4];
    #pragma unroll
    for (int t = 0; t < 4; t++)
        #pragma unroll
        for (int u = 0; u < 4; u++)
            #pragma unroll
            for (int r = 0; r < 4; r++)
                acc[t][u][r] = 0.f;

    float4 pa0, pa1, pb0;

    pa0 = *(const float4*)(Ab + (size_t)a_row * DIM + a_cb);
    pa1 = *(const float4*)(Ab + (size_t)a_row * DIM + a_cb + 4);
    pb0 = *(const float4*)(Bb + (size_t)b_row * DIM + b_col);
    {
        unsigned* As0 = AsBase;
        unsigned* Bs0 = BsBase;
        As0[(a_cb + 0) * ASTR + a_row] = f2tf32(pa0.x);
        As0[(a_cb + 1) * ASTR + a_row] = f2tf32(pa0.y);
        As0[(a_cb + 2) * ASTR + a_row] = f2tf32(pa0.z);
        As0[(a_cb + 3) * ASTR + a_row] = f2tf32(pa0.w);
        As0[(a_cb + 4) * ASTR + a_row] = f2tf32(pa1.x);
        As0[(a_cb + 5) * ASTR + a_row] = f2tf32(pa1.y);
        As0[(a_cb + 6) * ASTR + a_row] = f2tf32(pa1.z);
        As0[(a_cb + 7) * ASTR + a_row] = f2tf32(pa1.w);
        uint4 bv;
        bv.x = f2tf32(pb0.x); bv.y = f2tf32(pb0.y);
        bv.z = f2tf32(pb0.z); bv.w = f2tf32(pb0.w);
        *(uint4*)(&Bs0[b_row * BSTR + b_col]) = bv;
    }
    __syncthreads();

    const int NT = DIM / GBK;
    int cur = 0;
    for (int t0 = 0; t0 < NT; t0++) {
        const bool has_next = (t0 + 1) < NT;
        if (has_next) {
            const int kn = (t0 + 1) * GBK;
            pa0 = *(const float4*)(Ab + (size_t)a_row * DIM + kn + a_cb);
            pa1 = *(const float4*)(Ab + (size_t)a_row * DIM + kn + a_cb + 4);
            pb0 = *(const float4*)(Bb + (size_t)(kn + b_row) * DIM + b_col);
        }

        const unsigned* Asc = AsBase + cur * GEMM_A_BUF;
        const unsigned* Bsc = BsBase + cur * GEMM_B_BUF;
        #pragma unroll
        for (int kb = 0; kb < GBK; kb += 8) {
            unsigned af0[4], af1[4], af2[4], af3[4], bf0[4], bf1[4];
            #pragma unroll
            for (int t = 0; t < 4; t++) {
                const int m0 = mb + t * 16 + gid;
                af0[t] = Asc[(kb + tg    ) * ASTR + m0];
                af1[t] = Asc[(kb + tg    ) * ASTR + m0 + 8];
                af2[t] = Asc[(kb + tg + 4) * ASTR + m0];
                af3[t] = Asc[(kb + tg + 4) * ASTR + m0 + 8];
            }
            #pragma unroll
            for (int u = 0; u < 4; u++) {
                const int n0 = nb + u * 8 + gid;
                bf0[u] = Bsc[(kb + tg    ) * BSTR + n0];
                bf1[u] = Bsc[(kb + tg + 4) * BSTR + n0];
            }
            #pragma unroll
            for (int t = 0; t < 4; t++)
                #pragma unroll
                for (int u = 0; u < 4; u++)
                    mma_tf32(acc[t][u], af0[t], af1[t], af2[t], af3[t],
                             bf0[u], bf1[u]);
        }

        if (has_next) {
            const int nxt = cur ^ 1;
            unsigned* Asn = AsBase + nxt * GEMM_A_BUF;
            unsigned* Bsn = BsBase + nxt * GEMM_B_BUF;
            Asn[(a_cb + 0) * ASTR + a_row] = f2tf32(pa0.x);
            Asn[(a_cb + 1) * ASTR + a_row] = f2tf32(pa0.y);
            Asn[(a_cb + 2) * ASTR + a_row] = f2tf32(pa0.z);
            Asn[(a_cb + 3) * ASTR + a_row] = f2tf32(pa0.w);
            Asn[(a_cb + 4) * ASTR + a_row] = f2tf32(pa1.x);
            Asn[(a_cb + 5) * ASTR + a_row] = f2tf32(pa1.y);
            Asn[(a_cb + 6) * ASTR + a_row] = f2tf32(pa1.z);
            Asn[(a_cb + 7) * ASTR + a_row] = f2tf32(pa1.w);
            uint4 bv;
            bv.x = f2tf32(pb0.x); bv.y = f2tf32(pb0.y);
            bv.z = f2tf32(pb0.z); bv.w = f2tf32(pb0.w);
            *(uint4*)(&Bsn[b_row * BSTR + b_col]) = bv;
            cur = nxt;
            __syncthreads();
        }
    }

    #pragma unroll
    for (int t = 0; t < 4; t++) {
        const int row0 = by * GBM + mb + t * 16 + gid;
        #pragma unroll
        for (int u = 0; u < 4; u++) {
            const int col = bx * GBN + nb + u * 8 + tg * 2;
            const float2 bv = *(const float2*)(bias + col);
            float2 c0, c1;
            c0.x = alpha * (acc[t][u][0] + bv.x);
            c0.y = alpha * (acc[t][u][1] + bv.y);
            c1.x = alpha * (acc[t][u][2] + bv.x);
            c1.y = alpha * (acc[t][u][3] + bv.y);
            *(float2*)(C + (size_t)row0 * DIM + col)       = c0;
            *(float2*)(C + (size_t)(row0 + 8) * DIM + col) = c1;
        }
    }
}

// ---------------------------------------------------------------------------
// Flash attention v4: warp tile 32q x 64k, 4 warps / 128 queries, no P smem.
//
// vs v3.1: (1) K/V B-fragments were loaded identically by 8 warps; with 4
// warps of 32 rows the duplication halves. (2) The P staging buffer is gone:
// the PV A-fragment (rows gid/gid+8, cols tg/tg+4 of each 16x8 P block) is
// built from the S accumulators (rows gid/gid+8, cols 2tg/2tg+1) by lane
// shuffles — src lane gid*4 + (tg>>1) (+2 for the +4 column), element parity
// tg&1. acc_s is overwritten with tf32 bits right after softmax so shuffles
// move ready MMA operands.
//
// Layouts (banks = addr mod 32; gid=lane>>2, tg=lane&3):
//   Qs[d][q] FQSTR=136 (==8):  A-frag banks 8*tg+gid  ✓
//   Ks[k][d] KSTR_K=68 (==4):  B-frag banks 4*gid+tg  ✓
//   Vs[k][d] KSTR_V=72 (==8):  B-frag banks 8*tg+gid  ✓
// Smem 70912B -> 2 blocks/SM; ~200 regs/thread under __launch_bounds__(128,2).
// ---------------------------------------------------------------------------
#define FBQ    128
#define FBK    64
#define FQSTR  136
#define KSTR_K 68
#define KSTR_V 72

#define FQS_OFF 0                                   // Qs: 64*136 = 8704
#define FKS_OFF (FQS_OFF + D_HEAD * FQSTR)          // Ks: 64*68  = 4352
#define FVS_OFF (FKS_OFF + FBK * KSTR_K)            // Vs: 64*72  = 4608
#define FGS_OFF (FVS_OFF + FBK * KSTR_V)            // Gs: 64
#define FSMEM_WORDS (FGS_OFF + FBK)                 // 17728
#define FSMEM_BYTES (FSMEM_WORDS * 4)               // 70912

__global__ __launch_bounds__(128, 2) void flash_attn4_kernel(
    const int* __restrict__ mask, const float* __restrict__ gauss)
{
    extern __shared__ unsigned fsm[];
    unsigned* const Qs = fsm + FQS_OFF;
    unsigned* const Ks = fsm + FKS_OFF;
    unsigned* const Vs = fsm + FVS_OFF;
    float*    const Gs = (float*)(fsm + FGS_OFF);

    const int tid  = threadIdx.x;
    const int lane = tid & 31;
    const int wid  = tid >> 5;        // 0..3
    const int gid  = lane >> 2;       // 0..7
    const int tg   = lane & 3;        // 0..3
    const int mb   = wid * 32;        // warp's query-row base (32 rows)

    const int b     = blockIdx.z;
    const int h     = blockIdx.y;
    const int qbase = blockIdx.x * FBQ;

    // ---- load Q block transposed into Qs[d][q] as tf32 (once) ----
    {
        const float* qg = g_q + ((size_t)(b * SEQ + qbase)) * DIM + h * D_HEAD;
        #pragma unroll
        for (int c = 0; c < 16; c++) {
            int flat = (c * 128 + tid) * 4;       // 8192 floats
            int qr = flat >> 6;                    // 0..127
            int d  = flat & 63;
            float4 v = *(const float4*)(qg + (size_t)qr * DIM + d);
            Qs[(d + 0) * FQSTR + qr] = f2tf32(v.x);
            Qs[(d + 1) * FQSTR + qr] = f2tf32(v.y);
            Qs[(d + 2) * FQSTR + qr] = f2tf32(v.z);
            Qs[(d + 3) * FQSTR + qr] = f2tf32(v.w);
        }
    }

    // state: index [t*2 + rh], t = 16-row block (0,1), rh = row half (0,1)
    float m_run[4], l_run[4];
    float acc_o[2][8][4];             // [t][d-block][reg]
    #pragma unroll
    for (int i = 0; i < 4; i++) { m_run[i] = -1e30f; l_run[i] = 0.f; }
    #pragma unroll
    for (int t = 0; t < 2; t++)
        #pragma unroll
        for (int u = 0; u < 8; u++)
            #pragma unroll
            for (int r = 0; r < 4; r++) acc_o[t][u][r] = 0.f;

    for (int kt = 0; kt < SEQ; kt += FBK) {
        __syncthreads();   // Q ready (1st iter) / all warps done with prev K,V

        // ---- load K, V natural (tf32), Gs ----
        {
            const float* kg = g_k + ((size_t)(b * SEQ + kt)) * DIM + h * D_HEAD;
            const float* vg = g_v + ((size_t)(b * SEQ + kt)) * DIM + h * D_HEAD;
            #pragma unroll
            for (int c = 0; c < 8; c++) {
                int flat = (c * 128 + tid) * 4;    // 4096 floats each
                int kr = flat >> 6;                 // 0..63
                int d  = flat & 63;
                float4 kv = *(const float4*)(kg + (size_t)kr * DIM + d);
                float4 vv = *(const float4*)(vg + (size_t)kr * DIM + d);
                uint4 ku, vu;
                ku.x = f2tf32(kv.x); ku.y = f2tf32(kv.y);
                ku.z = f2tf32(kv.z); ku.w = f2tf32(kv.w);
                vu.x = f2tf32(vv.x); vu.y = f2tf32(vv.y);
                vu.z = f2tf32(vv.z); vu.w = f2tf32(vv.w);
                *(uint4*)(Ks + kr * KSTR_K + d) = ku;
                *(uint4*)(Vs + kr * KSTR_V + d) = vu;
            }
            if (tid < FBK) {
                int kk = kt + tid;
                float g = gauss[b * SEQ + kk] + 1e-10f;
                Gs[tid] = (mask[b * SEQ + kk] == 0) ? 0.f : g;
            }
        }
        __syncthreads();   // tile visible

        // ---- S = Q · K^T : warp tile 32(q) x 64(k), K-dim = 64 ----
        float acc_s[2][8][4];
        #pragma unroll
        for (int t = 0; t < 2; t++)
            #pragma unroll
            for (int u = 0; u < 8; u++)
                #pragma unroll
                for (int r = 0; r < 4; r++) acc_s[t][u][r] = 0.f;

        #pragma unroll
        for (int kb = 0; kb < D_HEAD; kb += 8) {
            unsigned af0[2], af1[2], af2[2], af3[2], bf0[8], bf1[8];
            #pragma unroll
            for (int t = 0; t < 2; t++) {
                const int m0 = mb + t * 16 + gid;
                af0[t] = Qs[(kb + tg    ) * FQSTR + m0];
                af1[t] = Qs[(kb + tg    ) * FQSTR + m0 + 8];
                af2[t] = Qs[(kb + tg + 4) * FQSTR + m0];
                af3[t] = Qs[(kb + tg + 4) * FQSTR + m0 + 8];
            }
            #pragma unroll
            for (int u = 0; u < 8; u++) {
                const int n0 = u * 8 + gid;        // key index
                bf0[u] = Ks[n0 * KSTR_K + kb + tg    ];
                bf1[u] = Ks[n0 * KSTR_K + kb + tg + 4];
            }
            #pragma unroll
            for (int t = 0; t < 2; t++)
                #pragma unroll
                for (int u = 0; u < 8; u++)
                    mma_tf32(acc_s[t][u], af0[t], af1[t], af2[t], af3[t],
                             bf0[u], bf1[u]);
        }

        // ---- online softmax (FMA-pipe exp), gauss/mask folded ----
        float g2v[8][2];
        #pragma unroll
        for (int u = 0; u < 8; u++) {
            float2 gg = *(const float2*)(Gs + u * 8 + tg * 2);
            g2v[u][0] = gg.x; g2v[u][1] = gg.y;
        }

        #pragma unroll
        for (int t = 0; t < 2; t++) {
            #pragma unroll
            for (int rh = 0; rh < 2; rh++) {
                const int si = t * 2 + rh;
                float lm = -1e30f;
                #pragma unroll
                for (int u = 0; u < 8; u++) {
                    float e0 = (g2v[u][0] > 0.f) ? acc_s[t][u][rh*2+0] : -1e30f;
                    float e1 = (g2v[u][1] > 0.f) ? acc_s[t][u][rh*2+1] : -1e30f;
                    lm = fmaxf(lm, fmaxf(e0, e1));
                }
                lm = fmaxf(lm, __shfl_xor_sync(0xffffffffu, lm, 1));
                lm = fmaxf(lm, __shfl_xor_sync(0xffffffffu, lm, 2));

                const float mnew = fmaxf(m_run[si], lm);
                const float scl  = fast_exp2((m_run[si] - mnew) * LOG2E);
                const float mlg  = mnew * LOG2E;
                float rs = 0.f;
                #pragma unroll
                for (int u = 0; u < 8; u++) {
                    #pragma unroll
                    for (int c = 0; c < 2; c++) {
                        float x = fmaf(acc_s[t][u][rh*2+c], LOG2E, -mlg);
                        float p = fast_exp2(x) * g2v[u][c];
                        rs += p;
                        // store tf32 operand bits in place for the PV shuffles
                        acc_s[t][u][rh*2+c] = __uint_as_float(f2tf32(p));
                    }
                }
                rs += __shfl_xor_sync(0xffffffffu, rs, 1);
                rs += __shfl_xor_sync(0xffffffffu, rs, 2);

                l_run[si] = l_run[si] * scl + rs;
                m_run[si] = mnew;
                #pragma unroll
                for (int u = 0; u < 8; u++) {
                    acc_o[t][u][rh*2+0] *= scl;
                    acc_o[t][u][rh*2+1] *= scl;
                }
            }
        }

        // ---- O += P · V : A-frags via shuffle from acc_s (no smem) ----
        const int src0 = (gid << 2) + (tg >> 1);
        const int src1 = src0 + 2;
        const bool odd = (tg & 1);
        #pragma unroll
        for (int kb = 0; kb < FBK; kb += 8) {
            const int u = kb >> 3;
            unsigned pa0[2], pa1[2], pa2[2], pa3[2];
            #pragma unroll
            for (int t = 0; t < 2; t++) {
                float v0 = __shfl_sync(0xffffffffu, acc_s[t][u][0], src0);
                float v1 = __shfl_sync(0xffffffffu, acc_s[t][u][1], src0);
                float v2 = __shfl_sync(0xffffffffu, acc_s[t][u][2], src0);
                float v3 = __shfl_sync(0xffffffffu, acc_s[t][u][3], src0);
                float w0 = __shfl_sync(0xffffffffu, acc_s[t][u][0], src1);
                float w1 = __shfl_sync(0xffffffffu, acc_s[t][u][1], src1);
                float w2 = __shfl_sync(0xffffffffu, acc_s[t][u][2], src1);
                float w3 = __shfl_sync(0xffffffffu, acc_s[t][u][3], src1);
                pa0[t] = __float_as_uint(odd ? v1 : v0);   // (gid,   tg)
                pa1[t] = __float_as_uint(odd ? v3 : v2);   // (gid+8, tg)
                pa2[t] = __float_as_uint(odd ? w1 : w0);   // (gid,   tg+4)
                pa3[t] = __float_as_uint(odd ? w3 : w2);   // (gid+8, tg+4)
            }
            unsigned bf0[8], bf1[8];
            #pragma unroll
            for (int j = 0; j < 8; j++) {
                const int n0 = j * 8 + gid;        // head-dim index
                bf0[j] = Vs[(kb + tg    ) * KSTR_V + n0];
                bf1[j] = Vs[(kb + tg + 4) * KSTR_V + n0];
            }
            #pragma unroll
            for (int t = 0; t < 2; t++)
                #pragma unroll
                for (int j = 0; j < 8; j++)
                    mma_tf32(acc_o[t][j], pa0[t], pa1[t], pa2[t], pa3[t],
                             bf0[j], bf1[j]);
        }
    }

    // ---- epilogue: normalize and store ----
    #pragma unroll
    for (int t = 0; t < 2; t++) {
        #pragma unroll
        for (int rh = 0; rh < 2; rh++) {
            const float inv = 1.f / l_run[t * 2 + rh];
            const int qrow = qbase + mb + t * 16 + gid + rh * 8;
            float* op = g_ctx + ((size_t)(b * SEQ + qrow)) * DIM + h * D_HEAD;
            #pragma unroll
            for (int j = 0; j < 8; j++) {
                float2 ov;
                ov.x = acc_o[t][j][rh*2+0] * inv;
                ov.y = acc_o[t][j][rh*2+1] * inv;
                *(float2*)(op + j * 8 + tg * 2) = ov;
            }
        }
    }
}

// ---------------------------------------------------------------------------
// Launch
// inputs: 0=query 1=key 2=value 3=mask 4=gauss_weight
//         5=Wq 6=bq 7=Wk 8=bk 9=Wv 10=bv 11=Wo 12=bo
// ---------------------------------------------------------------------------
extern "C" void kernel_launch(void* const* d_in, const int* in_sizes, int n_in,
                              void* d_out, int out_size)
{
    const float* query = (const float*)d_in[0];
    const float* key   = (const float*)d_in[1];
    const float* value = (const float*)d_in[2];
    const int*   mask  = (const int*)  d_in[3];
    const float* gauss = (const float*)d_in[4];
    const float* Wq = (const float*)d_in[5];
    const float* bq = (const float*)d_in[6];
    const float* Wk = (const float*)d_in[7];
    const float* bk = (const float*)d_in[8];
    const float* Wv = (const float*)d_in[9];
    const float* bv = (const float*)d_in[10];
    const float* Wo = (const float*)d_in[11];
    const float* bo = (const float*)d_in[12];
    float* out = (float*)d_out;

    float *pq, *pk, *pv, *pctx;
    cudaGetSymbolAddress((void**)&pq,   g_q);
    cudaGetSymbolAddress((void**)&pk,   g_k);
    cudaGetSymbolAddress((void**)&pv,   g_v);
    cudaGetSymbolAddress((void**)&pctx, g_ctx);

    // allow >48KB dynamic smem (idempotent host calls, not stream ops ->
    // safe under graph capture)
    cudaFuncSetAttribute(tf32_gemm_kernel,
                         cudaFuncAttributeMaxDynamicSharedMemorySize,
                         GEMM_SMEM_BYTES);
    cudaFuncSetAttribute(flash_attn4_kernel,
                         cudaFuncAttributeMaxDynamicSharedMemorySize,
                         FSMEM_BYTES);

    dim3 ggrid(DIM / GBN, MROWS / GBM);   // (8, 16) = 128 blocks
    const float qscale = 1.0f / 8.0f;     // 1/sqrt(D_HEAD)

    tf32_gemm_kernel<<<ggrid, 512, GEMM_SMEM_BYTES>>>(query, Wq, bq, pq, qscale);
    tf32_gemm_kernel<<<ggrid, 512, GEMM_SMEM_BYTES>>>(key,   Wk, bk, pk, 1.0f);
    tf32_gemm_kernel<<<ggrid, 512, GEMM_SMEM_BYTES>>>(value, Wv, bv, pv, 1.0f);

    dim3 agrid(SEQ / FBQ, N_HEADS, BS);   // (8, 16, 4)
    flash_attn4_kernel<<<agrid, 128, FSMEM_BYTES>>>(mask, gauss);

    tf32_gemm_kernel<<<ggrid, 512, GEMM_SMEM_BYTES>>>(pctx, Wo, bo, out, 1.0f);
}